// round 1
// baseline (speedup 1.0000x reference)
#include <cuda_runtime.h>
#include <math.h>

#define HID  4096
#define NH   32
#define DD   128
#define II   4096        // NH*DD
#define EPSF 1e-6f

// ---------------- scratch (no allocations allowed) ----------------
__device__ float g_qkv[3 * II];   // raw qkv pre-conv
__device__ float g_z[II];
__device__ float g_a[NH];
__device__ float g_b[NH];
__device__ float g_c[II];         // core * silu(z), input to out-proj

// ---------------- Kernel A: fused GEMV (W_qkv | W_z | W_a | W_b) ----------------
// warp-per-row, float4 loads, input vector staged in shared.
__global__ void __launch_bounds__(256) gemv_fused_in(
    const float* __restrict__ hs,
    const float* __restrict__ Wqkv,
    const float* __restrict__ Wz,
    const float* __restrict__ Wa,
    const float* __restrict__ Wb)
{
    __shared__ float4 sh[HID / 4];
    const int tid = threadIdx.x;
    const float4* h4 = (const float4*)hs;
    #pragma unroll
    for (int i = tid; i < HID / 4; i += 256) sh[i] = h4[i];
    __syncthreads();

    const int warp = tid >> 5;
    const int lane = tid & 31;
    const int row  = blockIdx.x * 8 + warp;

    const float* Wrow;
    float* outp;
    if (row < 3 * II)               { Wrow = Wqkv + (size_t)row * HID;              outp = &g_qkv[row]; }
    else if (row < 4 * II)          { Wrow = Wz   + (size_t)(row - 3 * II) * HID;   outp = &g_z[row - 3 * II]; }
    else if (row < 4 * II + NH)     { Wrow = Wa   + (size_t)(row - 4 * II) * HID;   outp = &g_a[row - 4 * II]; }
    else if (row < 4 * II + 2 * NH) { Wrow = Wb   + (size_t)(row - 4 * II - NH) * HID; outp = &g_b[row - 4 * II - NH]; }
    else return;

    const float4* W4 = (const float4*)Wrow;
    float a0 = 0.f, a1 = 0.f, a2 = 0.f, a3 = 0.f;
    #pragma unroll
    for (int j = lane; j < HID / 4; j += 128) {
        float4 w0 = W4[j      ]; float4 x0 = sh[j      ];
        float4 w1 = W4[j +  32]; float4 x1 = sh[j +  32];
        float4 w2 = W4[j +  64]; float4 x2 = sh[j +  64];
        float4 w3 = W4[j +  96]; float4 x3 = sh[j +  96];
        a0 += w0.x*x0.x + w0.y*x0.y + w0.z*x0.z + w0.w*x0.w;
        a1 += w1.x*x1.x + w1.y*x1.y + w1.z*x1.z + w1.w*x1.w;
        a2 += w2.x*x2.x + w2.y*x2.y + w2.z*x2.z + w2.w*x2.w;
        a3 += w3.x*x3.x + w3.y*x3.y + w3.z*x3.z + w3.w*x3.w;
    }
    float acc = (a0 + a1) + (a2 + a3);
    #pragma unroll
    for (int o = 16; o; o >>= 1) acc += __shfl_xor_sync(0xffffffffu, acc, o);
    if (lane == 0) *outp = acc;
}

// ---------------- Kernel B: conv + gating + delta-rule state update ----------------
__device__ __forceinline__ float blockSum128(float x, float* s) {
    #pragma unroll
    for (int o = 16; o; o >>= 1) x += __shfl_xor_sync(0xffffffffu, x, o);
    const int w = threadIdx.x >> 5;
    __syncthreads();                 // protect s from previous use
    if ((threadIdx.x & 31) == 0) s[w] = x;
    __syncthreads();
    return s[0] + s[1] + s[2] + s[3];
}

__device__ __forceinline__ float siluf(float y) { return y / (1.f + expf(-y)); }

__global__ void __launch_bounds__(128) state_update(
    const float* __restrict__ rnn_state,
    const float* __restrict__ conv_state,
    const float* __restrict__ conv_w,
    const float* __restrict__ conv_b,
    const float* __restrict__ A_log,
    const float* __restrict__ dt_bias,
    const float* __restrict__ norm_w,
    float* __restrict__ out_state,     // d_out + II
    float* __restrict__ out_conv)      // d_out + II + NH*DD*DD
{
    const int h = blockIdx.x;
    const int e = threadIdx.x;         // 0..127

    __shared__ float s_red[4];
    __shared__ float s_qn[DD];
    __shared__ float s_kn[DD];

    // conv + silu for this head's q/k/v channels; write new_conv_state
    float vals[3];
    #pragma unroll
    for (int part = 0; part < 3; part++) {
        const int c = part * II + h * DD + e;
        const float c0 = conv_state[c * 3 + 0];
        const float c1 = conv_state[c * 3 + 1];
        const float c2 = conv_state[c * 3 + 2];
        const float xn = g_qkv[c];
        const float y = c0 * conv_w[c * 4 + 0] + c1 * conv_w[c * 4 + 1]
                      + c2 * conv_w[c * 4 + 2] + xn * conv_w[c * 4 + 3]
                      + conv_b[c];
        vals[part] = siluf(y);
        out_conv[c * 3 + 0] = c1;
        out_conv[c * 3 + 1] = c2;
        out_conv[c * 3 + 2] = xn;
    }
    const float q = vals[0], k = vals[1], v = vals[2];

    // L2 norms
    const float qs = blockSum128(q * q, s_red);
    const float ks = blockSum128(k * k, s_red);
    const float qn = q / fmaxf(sqrtf(qs), EPSF) * 0.08838834764831845f; // 1/sqrt(128)
    const float kn = k / fmaxf(sqrtf(ks), EPSF);
    s_qn[e] = qn;
    s_kn[e] = kn;
    __syncthreads();

    // gating scalars (redundant per-thread; trivial cost)
    const float bb   = g_b[h];
    const float beta = 1.f / (1.f + expf(-bb));
    const float xg   = g_a[h] + dt_bias[h];
    const float sp   = (xg > 20.f) ? xg : log1pf(expf(xg));
    const float eg   = expf(-expf(A_log[h]) * sp);

    const float* st  = rnn_state + (size_t)h * DD * DD;
    float*       ost = out_state + (size_t)h * DD * DD;

    // pass 1: kv_mem[e] = eg * sum_d state[d,e]*kn[d]
    float kv = 0.f;
    #pragma unroll 8
    for (int d = 0; d < DD; d++) kv += st[d * DD + e] * s_kn[d];
    kv *= eg;
    const float delta = (v - kv) * beta;

    // pass 2: new state + core  (state is L2-hot from pass 1)
    float core = 0.f;
    #pragma unroll 8
    for (int d = 0; d < DD; d++) {
        const float ns = st[d * DD + e] * eg + s_kn[d] * delta;
        ost[d * DD + e] = ns;
        core += ns * s_qn[d];
    }

    // RMS norm over e, gate with silu(z), stash for out-projection
    const float var = blockSum128(core * core, s_red) * (1.f / DD);
    const float cn  = norm_w[e] * core * rsqrtf(var + EPSF);
    const float zz  = g_z[h * DD + e];
    g_c[h * DD + e] = cn * siluf(zz);
}

// ---------------- Kernel C: out = W_out @ c ----------------
__global__ void __launch_bounds__(256) gemv_out(
    const float* __restrict__ Wout,
    float* __restrict__ out)
{
    __shared__ float4 sh[II / 4];
    const int tid = threadIdx.x;
    const float4* c4 = (const float4*)g_c;
    #pragma unroll
    for (int i = tid; i < II / 4; i += 256) sh[i] = c4[i];
    __syncthreads();

    const int warp = tid >> 5;
    const int lane = tid & 31;
    const int row  = blockIdx.x * 8 + warp;
    if (row >= HID) return;

    const float4* W4 = (const float4*)(Wout + (size_t)row * II);
    float a0 = 0.f, a1 = 0.f, a2 = 0.f, a3 = 0.f;
    #pragma unroll
    for (int j = lane; j < II / 4; j += 128) {
        float4 w0 = W4[j      ]; float4 x0 = sh[j      ];
        float4 w1 = W4[j +  32]; float4 x1 = sh[j +  32];
        float4 w2 = W4[j +  64]; float4 x2 = sh[j +  64];
        float4 w3 = W4[j +  96]; float4 x3 = sh[j +  96];
        a0 += w0.x*x0.x + w0.y*x0.y + w0.z*x0.z + w0.w*x0.w;
        a1 += w1.x*x1.x + w1.y*x1.y + w1.z*x1.z + w1.w*x1.w;
        a2 += w2.x*x2.x + w2.y*x2.y + w2.z*x2.z + w2.w*x2.w;
        a3 += w3.x*x3.x + w3.y*x3.y + w3.z*x3.z + w3.w*x3.w;
    }
    float acc = (a0 + a1) + (a2 + a3);
    #pragma unroll
    for (int o = 16; o; o >>= 1) acc += __shfl_xor_sync(0xffffffffu, acc, o);
    if (lane == 0) out[row] = acc;
}

// ---------------- launch ----------------
extern "C" void kernel_launch(void* const* d_in, const int* in_sizes, int n_in,
                              void* d_out, int out_size)
{
    const float* hs   = (const float*)d_in[0];
    const float* rnn  = (const float*)d_in[1];
    const float* cs   = (const float*)d_in[2];
    const float* Wqkv = (const float*)d_in[3];
    const float* Wz   = (const float*)d_in[4];
    const float* Wa   = (const float*)d_in[5];
    const float* Wb   = (const float*)d_in[6];
    const float* cw   = (const float*)d_in[7];
    const float* cb   = (const float*)d_in[8];
    const float* Alog = (const float*)d_in[9];
    const float* dtb  = (const float*)d_in[10];
    const float* nw   = (const float*)d_in[11];
    const float* Wout = (const float*)d_in[12];
    float* out = (float*)d_out;

    const int rowsA = 3 * II + II + 2 * NH;        // 16448
    gemv_fused_in<<<(rowsA + 7) / 8, 256>>>(hs, Wqkv, Wz, Wa, Wb);
    state_update<<<NH, DD>>>(rnn, cs, cw, cb, Alog, dtb, nw,
                             out + II, out + II + (size_t)NH * DD * DD);
    gemv_out<<<HID / 8, 256>>>(Wout, out);
}